// round 15
// baseline (speedup 1.0000x reference)
#include <cuda_runtime.h>
#include <cuda_fp16.h>
#include <cstdint>
#include <math.h>

#define BATCH 4
#define SEQ   2048
#define DMODEL 1024
#define NH    8
#define HD    128
#define HDIM  1024

// ---------------------------------------------------------------------------
// Scratch (device globals: allocation-free rule)
// ---------------------------------------------------------------------------
__device__ __half g_q[(size_t)BATCH * NH * SEQ * HD];        // [B,H,T,D]
__device__ __half g_k[(size_t)BATCH * NH * SEQ * HD];
__device__ __half g_v[(size_t)BATCH * NH * HD * SEQ];        // [B,H,D,T]
__device__ __half g_x[(size_t)BATCH * SEQ * DMODEL];
__device__ __half g_wq[(size_t)3 * HDIM * DMODEL];
__device__ __half g_wp[(size_t)DMODEL * HDIM];
__device__ __half g_y[(size_t)BATCH * SEQ * HDIM];
__device__ float  g_trig[(size_t)SEQ * 64];                  // [t][32][{cos,sin}]

// ---------------------------------------------------------------------------
// PTX helpers
// ---------------------------------------------------------------------------
__device__ __forceinline__ uint32_t smem_u32(const void* p) {
    uint32_t a;
    asm("{ .reg .u64 t; cvta.to.shared.u64 t, %1; cvt.u32.u64 %0, t; }"
        : "=r"(a) : "l"(p));
    return a;
}

#define LDMX4(r, addr) \
    asm volatile("ldmatrix.sync.aligned.m8n8.x4.shared.b16 {%0,%1,%2,%3}, [%4];" \
        : "=r"((r)[0]), "=r"((r)[1]), "=r"((r)[2]), "=r"((r)[3]) : "r"(addr))

#define MMA_F16(d, a, b0, b1) \
    asm volatile("mma.sync.aligned.m16n8k16.row.col.f32.f16.f16.f32 " \
        "{%0,%1,%2,%3},{%4,%5,%6,%7},{%8,%9},{%0,%1,%2,%3};" \
        : "+f"((d)[0]), "+f"((d)[1]), "+f"((d)[2]), "+f"((d)[3]) \
        : "r"((a)[0]), "r"((a)[1]), "r"((a)[2]), "r"((a)[3]), "r"(b0), "r"(b1))

#define CP_ASYNC16(dst, src) \
    asm volatile("cp.async.cg.shared.global [%0], [%1], 16;" :: "r"(dst), "l"(src) : "memory")
#define CP_COMMIT() asm volatile("cp.async.commit_group;" ::: "memory")
#define CP_WAIT0()  asm volatile("cp.async.wait_group 0;" ::: "memory")
#define CP_WAIT1()  asm volatile("cp.async.wait_group 1;" ::: "memory")
#define CP_WAIT2()  asm volatile("cp.async.wait_group 2;" ::: "memory")
#define CP_WAIT3()  asm volatile("cp.async.wait_group 3;" ::: "memory")

__device__ __forceinline__ uint32_t packh(float e0, float e1) {
    __half2 h = __floats2half2_rn(e0, e1);
    return *reinterpret_cast<uint32_t*>(&h);
}

// ---------------------------------------------------------------------------
// conv: fp32 -> fp16; trig table precompute
// ---------------------------------------------------------------------------
__global__ __launch_bounds__(256) void conv_kernel(
    const float* __restrict__ src, __half* __restrict__ dst, int n4)
{
    int i = blockIdx.x * 256 + threadIdx.x;
    if (i < n4) {
        float4 v = ((const float4*)src)[i];
        ((uint2*)dst)[i] = make_uint2(packh(v.x, v.y), packh(v.z, v.w));
    }
}

__global__ __launch_bounds__(256) void trig_kernel(float* __restrict__ tg)
{
    const int idx = blockIdx.x * 256 + threadIdx.x;   // 65536 (t,i) pairs
    const int t = idx >> 5, i = idx & 31;
    const float xi = (float)i / 31.0f;
    const float f = (float)exp2(-10.0 * (double)xi);
    const float th = (float)t * f;
    tg[t * 64 + i * 2]     = cosf(th);
    tg[t * 64 + i * 2 + 1] = sinf(th);
}

// ===========================================================================
// fp16 GEMM: C[M,N](fp32) = A[M,K] @ B[N,K]^T. CTA 256x128, 512 thr,
// K-chunk 32, 4-stage cp.async. fused=1: qkv epilogue (RMS+RoPE+v-mix+layout).
// ===========================================================================
#define GA_PART  20480
#define GB_PART  10240
#define G_STAGE  (GA_PART + GB_PART)              // 30720
#define G_SMEM   204800                           // epilogue tile needs 201728

__global__ __launch_bounds__(512, 1) void gemm_f16(
    const __half* __restrict__ A, const __half* __restrict__ B,
    float* __restrict__ C, int Kd, int Nd, int fused,
    __half* __restrict__ Qg, __half* __restrict__ Kg, __half* __restrict__ Vg,
    const float* __restrict__ ve, const float* __restrict__ lam,
    const float* __restrict__ trig_g)
{
    extern __shared__ char smem[];
    const uint32_t sb = smem_u32(smem);
    const int tid = threadIdx.x;
    const int wid = tid >> 5, lane = tid & 31;
    const int wm = wid >> 2, wn = wid & 3;
    const int m0 = blockIdx.y * 256, n0 = blockIdx.x * 128;
    const int nch = Kd / 32;

    auto load_stage = [&](int c) {
        const uint32_t st = sb + (c & 3) * G_STAGE;
        const __half* pA = A + (size_t)m0 * Kd + c * 32;
        const __half* pB = B + (size_t)n0 * Kd + c * 32;
#pragma unroll
        for (int i = 0; i < 2; i++) {
            const int cc = i * 512 + tid;
            const int row = cc >> 2, col = cc & 3;
            CP_ASYNC16(st + row * 80 + col * 16, pA + (size_t)row * Kd + col * 8);
        }
        {
            const int row = tid >> 2, col = tid & 3;
            CP_ASYNC16(st + GA_PART + row * 80 + col * 16, pB + (size_t)row * Kd + col * 8);
        }
    };

    float acc[4][4][4];
#pragma unroll
    for (int i = 0; i < 4; i++)
#pragma unroll
        for (int j = 0; j < 4; j++)
#pragma unroll
            for (int e = 0; e < 4; e++) acc[i][j][e] = 0.f;

    auto compute = [&](int s) {
        const uint32_t st = sb + s * G_STAGE;
        const uint32_t lrow = (lane & 15);
        const uint32_t lcol = (lane >> 4) * 16;
#pragma unroll
        for (int k16 = 0; k16 < 2; k16++) {
            const uint32_t kb2 = k16 * 32;
            uint32_t a_[4][4];
#pragma unroll
            for (int i = 0; i < 4; i++)
                LDMX4(a_[i], st + (wm * 64 + i * 16 + lrow) * 80 + kb2 + lcol);
            uint32_t b_[4][2];
#pragma unroll
            for (int jj = 0; jj < 2; jj++) {
                uint32_t r[4];
                LDMX4(r, st + GA_PART + (wn * 32 + jj * 16 + lrow) * 80 + kb2 + lcol);
                b_[2 * jj][0] = r[0]; b_[2 * jj][1] = r[2];
                b_[2 * jj + 1][0] = r[1]; b_[2 * jj + 1][1] = r[3];
            }
#pragma unroll
            for (int i = 0; i < 4; i++)
#pragma unroll
                for (int j = 0; j < 4; j++)
                    MMA_F16(acc[i][j], a_[i], b_[j][0], b_[j][1]);
        }
    };

    load_stage(0); CP_COMMIT();
    load_stage(1); CP_COMMIT();
    load_stage(2); CP_COMMIT();
    for (int c = 0; c < nch; c++) {
        if (c + 2 < nch) CP_WAIT2();
        else if (c + 1 < nch) CP_WAIT1();
        else CP_WAIT0();
        __syncthreads();
        if (c + 3 < nch) { load_stage(c + 3); CP_COMMIT(); }
        compute(c & 3);
    }

    const int r = lane >> 2;
    const int cb = (lane & 3) * 2;

    if (!fused) {
#pragma unroll
        for (int i = 0; i < 4; i++) {
            const int row0 = m0 + wm * 64 + i * 16 + r;
#pragma unroll
            for (int j = 0; j < 4; j++) {
                const int col = n0 + wn * 32 + j * 8 + cb;
                *(float2*)(C + (size_t)row0 * Nd + col) = make_float2(acc[i][j][0], acc[i][j][1]);
                *(float2*)(C + (size_t)(row0 + 8) * Nd + col) = make_float2(acc[i][j][2], acc[i][j][3]);
            }
        }
        return;
    }

    // ======================= fused qkv epilogue ==========================
    float* tile = (float*)smem;              // [256][132]
    float* rsc  = tile + 256 * 132;          // [256]
    float* trig = rsc + 256;                 // [256][32][2]

    __syncthreads();

#pragma unroll
    for (int i = 0; i < 4; i++) {
        const int row = wm * 64 + i * 16 + r;
#pragma unroll
        for (int j = 0; j < 4; j++) {
            const int col = wn * 32 + j * 8 + cb;
            *(float2*)(tile + row * 132 + col) = make_float2(acc[i][j][0], acc[i][j][1]);
            *(float2*)(tile + (row + 8) * 132 + col) = make_float2(acc[i][j][2], acc[i][j][3]);
        }
    }

    const int part = n0 >> 7;        // 0..23
    const int kind = part >> 3;      // 0=q 1=k 2=v
    const int h = part & 7;

    if (kind < 2) {
        __syncthreads();
        {
            const int row = tid >> 1, hs = tid & 1;
            const float* tr = tile + row * 132 + hs * 64;
            float s = 0.f;
#pragma unroll
            for (int k4 = 0; k4 < 16; k4++) {
                float4 v = *(const float4*)(tr + k4 * 4);
                s += v.x * v.x + v.y * v.y + v.z * v.z + v.w * v.w;
            }
            s += __shfl_xor_sync(0xffffffffu, s, 1);
            if (hs == 0)
                rsc[row] = rsqrtf(s * (1.0f / 128.0f) + 1.1920929e-7f);
        }
        for (int e = tid; e < 8192; e += 512) {
            const int row = e >> 5, i = e & 31;
            const int t = (m0 + row) & (SEQ - 1);
            ((float2*)trig)[e] = ((const float2*)trig_g)[t * 32 + i];
        }
        __syncthreads();

        const int dd = (tid & 63) * 2;
        const int rg = tid >> 6;
#pragma unroll 4
        for (int stp = 0; stp < 32; stp++) {
            const int row = rg + stp * 8;
            const float sc = rsc[row];
            float out[2];
#pragma unroll
            for (int e = 0; e < 2; e++) {
                const int d = dd + e;
                const float n = tile[row * 132 + d] * sc;
                const int il = d & 63;
                float cth, sth;
                if (il < 32) {
                    cth = trig[(row * 32 + il) * 2];
                    sth = trig[(row * 32 + il) * 2 + 1];
                } else { cth = 1.f; sth = 0.f; }
                const float partner = tile[row * 132 + (d < 64 ? d + 64 : d - 64)] * sc;
                out[e] = (d < 64) ? (n * cth + partner * sth)
                                  : (n * cth - partner * sth);
            }
            const int m = m0 + row;
            const int b = m >> 11, t = m & (SEQ - 1);
            const size_t o = (((size_t)(b * NH + h)) * SEQ + t) * HD + dd;
            if (kind == 0) *(uint32_t*)(Qg + o) = packh(out[0], out[1]);
            else           *(uint32_t*)(Kg + o) = packh(out[0], out[1]);
        }
    } else {
        const float l0 = lam[0], l1 = lam[1];
        __syncthreads();
        for (int e = tid; e < 32768; e += 512) {
            const int row = e >> 7, d = e & 127;
            const int m = m0 + row;
            const float vv = ve[(size_t)m * HDIM + h * HD + d];
            tile[row * 132 + d] = l0 * tile[row * 132 + d] + l1 * vv;
        }
        __syncthreads();
        const int d = tid >> 2;
        const int tq = (tid & 3) * 64;
        const int b = m0 >> 11, tbase = m0 & (SEQ - 1);
        const size_t obase = (((size_t)(b * NH + h)) * HD + d) * SEQ + tbase + tq;
#pragma unroll 8
        for (int k = 0; k < 64; k += 2) {
            const float v0 = tile[(tq + k) * 132 + d];
            const float v1 = tile[(tq + k + 1) * 132 + d];
            *(uint32_t*)(Vg + obase + k) = packh(v0, v1);
        }
    }
}

// ===========================================================================
// Flash attention, single fp16. 128 q-rows/CTA, 8 warps x 16 rows.
// Q fragments hoisted to registers (loop-invariant); K/V 4-stage cp.async.
// ===========================================================================
#define FQ_PART 34816
#define FK_PART 17408
#define FV_PART 18432
#define FSTAGE  (FK_PART + FV_PART)               // 35840
#define F_SMEM  (FQ_PART + 4 * FSTAGE)            // 178176

__global__ __launch_bounds__(256, 1) void flash_mma(
    const __half* __restrict__ Qg, const __half* __restrict__ Kg,
    const __half* __restrict__ Vg, __half* __restrict__ Yg)
{
    extern __shared__ char smem[];
    const uint32_t sbase = smem_u32(smem);
    const int tid = threadIdx.x;
    const int wid = tid >> 5, lane = tid & 31;
    const int qt = gridDim.x - 1 - blockIdx.x;      // big tiles first
    const int bh = blockIdx.y;
    const int b = bh >> 3, h = bh & 7;

    const size_t TD = (size_t)SEQ * HD;
    const __half* q_b = Qg + bh * TD;
    const __half* k_b = Kg + bh * TD;
    const __half* v_b = Vg + bh * TD;

#pragma unroll
    for (int i = 0; i < 8; i++) {
        int c = i * 256 + tid;
        int row = c >> 4, col = c & 15;
        CP_ASYNC16(sbase + row * 272 + col * 16,
                   q_b + (size_t)(qt * 128 + row) * 128 + col * 8);
    }
    auto load_kv = [&](int kt, int s) {
        uint32_t kb = sbase + FQ_PART + s * FSTAGE;
#pragma unroll
        for (int i = 0; i < 4; i++) {
            int c = i * 256 + tid;
            int row = c >> 4, col = c & 15;
            CP_ASYNC16(kb + row * 272 + col * 16,
                       k_b + (size_t)(kt * 64 + row) * 128 + col * 8);
        }
#pragma unroll
        for (int i = 0; i < 4; i++) {
            int c = i * 256 + tid;
            int row = c >> 3, col = c & 7;
            CP_ASYNC16(kb + FK_PART + row * 144 + col * 16,
                       v_b + (size_t)row * SEQ + kt * 64 + col * 8);
        }
    };
    const int nkt = 2 * qt + 2;
    load_kv(0, 0);
    CP_COMMIT();
    if (nkt > 1) { load_kv(1, 1); CP_COMMIT(); }
    if (nkt > 2) { load_kv(2, 2); CP_COMMIT(); }

    float acc[16][4];
#pragma unroll
    for (int i = 0; i < 16; i++)
#pragma unroll
        for (int e = 0; e < 4; e++) acc[i][e] = 0.f;
    float m_i[2] = {-1e30f, -1e30f};
    float l_i[2] = {0.f, 0.f};

    const uint32_t lrow = lane & 15;
    const uint32_t lcol = (lane >> 4) * 16;
    const float SC = 0.08838834764831845f;

    uint32_t qf[8][4];        // loop-invariant Q fragments (loaded at kt==0)

    for (int kt = 0; kt < nkt; kt++) {
        // prefetch kt+3 FIRST so the wait below has 4 groups in flight.
        if (kt + 3 < nkt) {
            load_kv(kt + 3, (kt + 3) & 3);
            CP_COMMIT();
            CP_WAIT3();
        } else if (kt + 2 < nkt) {
            CP_WAIT2();
        } else if (kt + 1 < nkt) {
            CP_WAIT1();
        } else {
            CP_WAIT0();
        }
        __syncthreads();
        const uint32_t kb = sbase + FQ_PART + (kt & 3) * FSTAGE;

        if (kt == 0) {
            const uint32_t qrow = sbase + (wid * 16 + lrow) * 272 + lcol;
#pragma unroll
            for (int k16 = 0; k16 < 8; k16++)
                LDMX4(qf[k16], qrow + k16 * 32);
        }

        float s[8][4];
#pragma unroll
        for (int j = 0; j < 8; j++)
#pragma unroll
            for (int e = 0; e < 4; e++) s[j][e] = 0.f;

#pragma unroll
        for (int k16 = 0; k16 < 8; k16++) {
            uint32_t kf[4][4];
#pragma unroll
            for (int jj = 0; jj < 4; jj++)
                LDMX4(kf[jj], kb + (jj * 16 + lrow) * 272 + lcol + k16 * 32);
#pragma unroll
            for (int jj = 0; jj < 4; jj++) {
                MMA_F16(s[2 * jj], qf[k16], kf[jj][0], kf[jj][2]);
                MMA_F16(s[2 * jj + 1], qf[k16], kf[jj][1], kf[jj][3]);
            }
        }

        const bool need_mask = (kt >= 2 * qt);
#pragma unroll
        for (int hh = 0; hh < 2; hh++) {
            const int rowg = qt * 128 + wid * 16 + (lane >> 2) + hh * 8;
            float mt = -1e30f;
#pragma unroll
            for (int j = 0; j < 8; j++) {
#pragma unroll
                for (int e = 0; e < 2; e++) {
                    float v = s[j][2 * hh + e] * SC;
                    if (need_mask) {
                        int colg = kt * 64 + j * 8 + (lane & 3) * 2 + e;
                        if (colg > rowg) v = -1e30f;
                    }
                    s[j][2 * hh + e] = v;
                    mt = fmaxf(mt, v);
                }
            }
            mt = fmaxf(mt, __shfl_xor_sync(0xffffffffu, mt, 1));
            mt = fmaxf(mt, __shfl_xor_sync(0xffffffffu, mt, 2));
            float mn = fmaxf(m_i[hh], mt);
            float corr = __expf(m_i[hh] - mn);
            m_i[hh] = mn;
            float rs = 0.f;
#pragma unroll
            for (int j = 0; j < 8; j++) {
#pragma unroll
                for (int e = 0; e < 2; e++) {
                    float p = __expf(s[j][2 * hh + e] - mn);
                    s[j][2 * hh + e] = p;
                    rs += p;
                }
            }
            rs += __shfl_xor_sync(0xffffffffu, rs, 1);
            rs += __shfl_xor_sync(0xffffffffu, rs, 2);
            l_i[hh] = l_i[hh] * corr + rs;
#pragma unroll
            for (int ot = 0; ot < 16; ot++) {
                acc[ot][2 * hh] *= corr;
                acc[ot][2 * hh + 1] *= corr;
            }
        }

        const uint32_t vb = kb + FK_PART;
#pragma unroll
        for (int kk = 0; kk < 4; kk++) {
            const int j0 = 2 * kk, j1 = 2 * kk + 1;
            uint32_t p_[4];
            p_[0] = packh(s[j0][0], s[j0][1]);
            p_[1] = packh(s[j0][2], s[j0][3]);
            p_[2] = packh(s[j1][0], s[j1][1]);
            p_[3] = packh(s[j1][2], s[j1][3]);
#pragma unroll
            for (int jp = 0; jp < 4; jp++) {
                const int ja = 2 * jp, jb2 = 2 * jp + 1;
                uint32_t rA[4], rB[4];
                LDMX4(rA, vb + (ja * 16 + lrow) * 144 + kk * 32 + lcol);
                LDMX4(rB, vb + (jb2 * 16 + lrow) * 144 + kk * 32 + lcol);
                MMA_F16(acc[2 * ja], p_, rA[0], rA[2]);
                MMA_F16(acc[2 * ja + 1], p_, rA[1], rA[3]);
                MMA_F16(acc[2 * jb2], p_, rB[0], rB[2]);
                MMA_F16(acc[2 * jb2 + 1], p_, rB[1], rB[3]);
            }
        }
        __syncthreads();
    }

    const float inv0 = 1.f / l_i[0];
    const float inv1 = 1.f / l_i[1];
    const int r0 = qt * 128 + wid * 16 + (lane >> 2);
    const int cb = (lane & 3) * 2;
#pragma unroll
    for (int ot = 0; ot < 16; ot++) {
        const int d = ot * 8 + cb;
        size_t o0 = ((size_t)b * SEQ + r0) * HDIM + h * HD + d;
        size_t o1 = o0 + (size_t)8 * HDIM;
        *(uint32_t*)(Yg + o0) = packh(acc[ot][0] * inv0, acc[ot][1] * inv0);
        *(uint32_t*)(Yg + o1) = packh(acc[ot][2] * inv1, acc[ot][3] * inv1);
    }
}

// ---------------------------------------------------------------------------
extern "C" void kernel_launch(void* const* d_in, const int* in_sizes, int n_in,
                              void* d_out, int out_size)
{
    const float* x        = (const float*)d_in[0];
    const float* ve       = (const float*)d_in[1];
    const float* qkv_w    = (const float*)d_in[2];   // [3*HDIM, DIM]
    const float* lambdas  = (const float*)d_in[3];
    const float* c_proj_w = (const float*)d_in[4];   // [DIM, HDIM]
    float* out = (float*)d_out;

    __half *Q, *K, *V, *X, *Wq, *Wp, *Y;
    float* Tg;
    cudaGetSymbolAddress((void**)&Q, g_q);
    cudaGetSymbolAddress((void**)&K, g_k);
    cudaGetSymbolAddress((void**)&V, g_v);
    cudaGetSymbolAddress((void**)&X, g_x);
    cudaGetSymbolAddress((void**)&Wq, g_wq);
    cudaGetSymbolAddress((void**)&Wp, g_wp);
    cudaGetSymbolAddress((void**)&Y, g_y);
    cudaGetSymbolAddress((void**)&Tg, g_trig);

    cudaFuncSetAttribute(gemm_f16, cudaFuncAttributeMaxDynamicSharedMemorySize, G_SMEM);
    cudaFuncSetAttribute(flash_mma, cudaFuncAttributeMaxDynamicSharedMemorySize, F_SMEM);

    // 0) operand conversion + trig table
    {
        int n4 = BATCH * SEQ * DMODEL / 4;
        conv_kernel<<<(n4 + 255) / 256, 256>>>(x, X, n4);
        n4 = 3 * HDIM * DMODEL / 4;
        conv_kernel<<<(n4 + 255) / 256, 256>>>(qkv_w, Wq, n4);
        n4 = DMODEL * HDIM / 4;
        conv_kernel<<<(n4 + 255) / 256, 256>>>(c_proj_w, Wp, n4);
        trig_kernel<<<SEQ * 32 / 256, 256>>>(Tg);
    }

    // 1) fused qkv GEMM + rms/rope/v-mix/layout -> Q,K,V
    gemm_f16<<<dim3(3 * HDIM / 128, BATCH * SEQ / 256), 512, G_SMEM>>>(
        X, Wq, nullptr, DMODEL, 3 * HDIM, 1, Q, K, V, ve, lambdas, Tg);

    // 2) flash attention (128 q-rows/CTA, 4-stage KV, Q frags in regs) -> Y
    flash_mma<<<dim3(SEQ / 128, BATCH * NH), 256, F_SMEM>>>(Q, K, V, Y);

    // 3) out = Y @ c_proj_w^T
    gemm_f16<<<dim3(DMODEL / 128, BATCH * SEQ / 256), 512, G_SMEM>>>(
        Y, Wp, out, HDIM, DMODEL, 0,
        nullptr, nullptr, nullptr, nullptr, nullptr, nullptr);
}

// round 16
// speedup vs baseline: 1.0090x; 1.0090x over previous
#include <cuda_runtime.h>
#include <cuda_fp16.h>
#include <cstdint>
#include <math.h>

#define BATCH 4
#define SEQ   2048
#define DMODEL 1024
#define NH    8
#define HD    128
#define HDIM  1024

// ---------------------------------------------------------------------------
// Scratch (device globals: allocation-free rule)
// ---------------------------------------------------------------------------
__device__ __half g_q[(size_t)BATCH * NH * SEQ * HD];        // [B,H,T,D]
__device__ __half g_k[(size_t)BATCH * NH * SEQ * HD];
__device__ __half g_v[(size_t)BATCH * NH * HD * SEQ];        // [B,H,D,T]
__device__ __half g_x[(size_t)BATCH * SEQ * DMODEL];
__device__ __half g_wq[(size_t)3 * HDIM * DMODEL];
__device__ __half g_wp[(size_t)DMODEL * HDIM];
__device__ __half g_y[(size_t)BATCH * SEQ * HDIM];
__device__ float  g_trig[(size_t)SEQ * 64];                  // [t][32][{cos,sin}]

// ---------------------------------------------------------------------------
// PTX helpers
// ---------------------------------------------------------------------------
__device__ __forceinline__ uint32_t smem_u32(const void* p) {
    uint32_t a;
    asm("{ .reg .u64 t; cvta.to.shared.u64 t, %1; cvt.u32.u64 %0, t; }"
        : "=r"(a) : "l"(p));
    return a;
}

#define LDMX4(r, addr) \
    asm volatile("ldmatrix.sync.aligned.m8n8.x4.shared.b16 {%0,%1,%2,%3}, [%4];" \
        : "=r"((r)[0]), "=r"((r)[1]), "=r"((r)[2]), "=r"((r)[3]) : "r"(addr))

#define MMA_F16(d, a, b0, b1) \
    asm volatile("mma.sync.aligned.m16n8k16.row.col.f32.f16.f16.f32 " \
        "{%0,%1,%2,%3},{%4,%5,%6,%7},{%8,%9},{%0,%1,%2,%3};" \
        : "+f"((d)[0]), "+f"((d)[1]), "+f"((d)[2]), "+f"((d)[3]) \
        : "r"((a)[0]), "r"((a)[1]), "r"((a)[2]), "r"((a)[3]), "r"(b0), "r"(b1))

#define CP_ASYNC16(dst, src) \
    asm volatile("cp.async.cg.shared.global [%0], [%1], 16;" :: "r"(dst), "l"(src) : "memory")
#define CP_COMMIT() asm volatile("cp.async.commit_group;" ::: "memory")
#define CP_WAIT0()  asm volatile("cp.async.wait_group 0;" ::: "memory")
#define CP_WAIT1()  asm volatile("cp.async.wait_group 1;" ::: "memory")
#define CP_WAIT2()  asm volatile("cp.async.wait_group 2;" ::: "memory")
#define CP_WAIT3()  asm volatile("cp.async.wait_group 3;" ::: "memory")

__device__ __forceinline__ uint32_t packh(float e0, float e1) {
    __half2 h = __floats2half2_rn(e0, e1);
    return *reinterpret_cast<uint32_t*>(&h);
}

// ---------------------------------------------------------------------------
// prep_all: merged fp32->fp16 conversions (x, Wq, Wp) + RoPE trig table.
// One launch; block ranges select the job. Per-block work identical to the
// previous separate kernels.
//   x:  n4 = 2097152 -> 8192 blocks   [0, 8192)
//   Wq: n4 =  786432 -> 3072 blocks   [8192, 11264)
//   Wp: n4 =  262144 -> 1024 blocks   [11264, 12288)
//   trig: 65536 pairs -> 256 blocks   [12288, 12544)
// ---------------------------------------------------------------------------
#define PB_X   8192
#define PB_WQ  3072
#define PB_WP  1024
#define PB_TR  256
#define PB_ALL (PB_X + PB_WQ + PB_WP + PB_TR)

__global__ __launch_bounds__(256) void prep_all(
    const float* __restrict__ x,  __half* __restrict__ X,
    const float* __restrict__ wq, __half* __restrict__ Wq,
    const float* __restrict__ wp, __half* __restrict__ Wp,
    float* __restrict__ tg)
{
    const int blk = blockIdx.x;
    if (blk < PB_X + PB_WQ + PB_WP) {
        const float* src;
        __half* dst;
        int i;
        if (blk < PB_X) {
            src = x; dst = X; i = blk * 256 + threadIdx.x;
        } else if (blk < PB_X + PB_WQ) {
            src = wq; dst = Wq; i = (blk - PB_X) * 256 + threadIdx.x;
        } else {
            src = wp; dst = Wp; i = (blk - PB_X - PB_WQ) * 256 + threadIdx.x;
        }
        float4 v = ((const float4*)src)[i];
        ((uint2*)dst)[i] = make_uint2(packh(v.x, v.y), packh(v.z, v.w));
    } else {
        const int idx = (blk - PB_X - PB_WQ - PB_WP) * 256 + threadIdx.x;
        const int t = idx >> 5, i = idx & 31;
        const float xi = (float)i / 31.0f;
        const float f = (float)exp2(-10.0 * (double)xi);
        const float th = (float)t * f;
        tg[t * 64 + i * 2]     = cosf(th);
        tg[t * 64 + i * 2 + 1] = sinf(th);
    }
}

// ===========================================================================
// fp16 GEMM: C[M,N](fp32) = A[M,K] @ B[N,K]^T. CTA 256x128, 512 thr,
// K-chunk 32, 4-stage cp.async. fused=1: qkv epilogue (RMS+RoPE+v-mix+layout).
// ===========================================================================
#define GA_PART  20480
#define GB_PART  10240
#define G_STAGE  (GA_PART + GB_PART)              // 30720
#define G_SMEM   204800                           // epilogue tile needs 201728

__global__ __launch_bounds__(512, 1) void gemm_f16(
    const __half* __restrict__ A, const __half* __restrict__ B,
    float* __restrict__ C, int Kd, int Nd, int fused,
    __half* __restrict__ Qg, __half* __restrict__ Kg, __half* __restrict__ Vg,
    const float* __restrict__ ve, const float* __restrict__ lam,
    const float* __restrict__ trig_g)
{
    extern __shared__ char smem[];
    const uint32_t sb = smem_u32(smem);
    const int tid = threadIdx.x;
    const int wid = tid >> 5, lane = tid & 31;
    const int wm = wid >> 2, wn = wid & 3;
    const int m0 = blockIdx.y * 256, n0 = blockIdx.x * 128;
    const int nch = Kd / 32;

    auto load_stage = [&](int c) {
        const uint32_t st = sb + (c & 3) * G_STAGE;
        const __half* pA = A + (size_t)m0 * Kd + c * 32;
        const __half* pB = B + (size_t)n0 * Kd + c * 32;
#pragma unroll
        for (int i = 0; i < 2; i++) {
            const int cc = i * 512 + tid;
            const int row = cc >> 2, col = cc & 3;
            CP_ASYNC16(st + row * 80 + col * 16, pA + (size_t)row * Kd + col * 8);
        }
        {
            const int row = tid >> 2, col = tid & 3;
            CP_ASYNC16(st + GA_PART + row * 80 + col * 16, pB + (size_t)row * Kd + col * 8);
        }
    };

    float acc[4][4][4];
#pragma unroll
    for (int i = 0; i < 4; i++)
#pragma unroll
        for (int j = 0; j < 4; j++)
#pragma unroll
            for (int e = 0; e < 4; e++) acc[i][j][e] = 0.f;

    auto compute = [&](int s) {
        const uint32_t st = sb + s * G_STAGE;
        const uint32_t lrow = (lane & 15);
        const uint32_t lcol = (lane >> 4) * 16;
#pragma unroll
        for (int k16 = 0; k16 < 2; k16++) {
            const uint32_t kb2 = k16 * 32;
            uint32_t a_[4][4];
#pragma unroll
            for (int i = 0; i < 4; i++)
                LDMX4(a_[i], st + (wm * 64 + i * 16 + lrow) * 80 + kb2 + lcol);
            uint32_t b_[4][2];
#pragma unroll
            for (int jj = 0; jj < 2; jj++) {
                uint32_t r[4];
                LDMX4(r, st + GA_PART + (wn * 32 + jj * 16 + lrow) * 80 + kb2 + lcol);
                b_[2 * jj][0] = r[0]; b_[2 * jj][1] = r[2];
                b_[2 * jj + 1][0] = r[1]; b_[2 * jj + 1][1] = r[3];
            }
#pragma unroll
            for (int i = 0; i < 4; i++)
#pragma unroll
                for (int j = 0; j < 4; j++)
                    MMA_F16(acc[i][j], a_[i], b_[j][0], b_[j][1]);
        }
    };

    load_stage(0); CP_COMMIT();
    load_stage(1); CP_COMMIT();
    load_stage(2); CP_COMMIT();
    for (int c = 0; c < nch; c++) {
        if (c + 2 < nch) CP_WAIT2();
        else if (c + 1 < nch) CP_WAIT1();
        else CP_WAIT0();
        __syncthreads();
        if (c + 3 < nch) { load_stage(c + 3); CP_COMMIT(); }
        compute(c & 3);
    }

    const int r = lane >> 2;
    const int cb = (lane & 3) * 2;

    if (!fused) {
#pragma unroll
        for (int i = 0; i < 4; i++) {
            const int row0 = m0 + wm * 64 + i * 16 + r;
#pragma unroll
            for (int j = 0; j < 4; j++) {
                const int col = n0 + wn * 32 + j * 8 + cb;
                *(float2*)(C + (size_t)row0 * Nd + col) = make_float2(acc[i][j][0], acc[i][j][1]);
                *(float2*)(C + (size_t)(row0 + 8) * Nd + col) = make_float2(acc[i][j][2], acc[i][j][3]);
            }
        }
        return;
    }

    // ======================= fused qkv epilogue ==========================
    float* tile = (float*)smem;              // [256][132]
    float* rsc  = tile + 256 * 132;          // [256]
    float* trig = rsc + 256;                 // [256][32][2]

    __syncthreads();

#pragma unroll
    for (int i = 0; i < 4; i++) {
        const int row = wm * 64 + i * 16 + r;
#pragma unroll
        for (int j = 0; j < 4; j++) {
            const int col = wn * 32 + j * 8 + cb;
            *(float2*)(tile + row * 132 + col) = make_float2(acc[i][j][0], acc[i][j][1]);
            *(float2*)(tile + (row + 8) * 132 + col) = make_float2(acc[i][j][2], acc[i][j][3]);
        }
    }

    const int part = n0 >> 7;        // 0..23
    const int kind = part >> 3;      // 0=q 1=k 2=v
    const int h = part & 7;

    if (kind < 2) {
        __syncthreads();
        {
            const int row = tid >> 1, hs = tid & 1;
            const float* tr = tile + row * 132 + hs * 64;
            float s = 0.f;
#pragma unroll
            for (int k4 = 0; k4 < 16; k4++) {
                float4 v = *(const float4*)(tr + k4 * 4);
                s += v.x * v.x + v.y * v.y + v.z * v.z + v.w * v.w;
            }
            s += __shfl_xor_sync(0xffffffffu, s, 1);
            if (hs == 0)
                rsc[row] = rsqrtf(s * (1.0f / 128.0f) + 1.1920929e-7f);
        }
        for (int e = tid; e < 8192; e += 512) {
            const int row = e >> 5, i = e & 31;
            const int t = (m0 + row) & (SEQ - 1);
            ((float2*)trig)[e] = ((const float2*)trig_g)[t * 32 + i];
        }
        __syncthreads();

        const int dd = (tid & 63) * 2;
        const int rg = tid >> 6;
#pragma unroll 4
        for (int stp = 0; stp < 32; stp++) {
            const int row = rg + stp * 8;
            const float sc = rsc[row];
            float out[2];
#pragma unroll
            for (int e = 0; e < 2; e++) {
                const int d = dd + e;
                const float n = tile[row * 132 + d] * sc;
                const int il = d & 63;
                float cth, sth;
                if (il < 32) {
                    cth = trig[(row * 32 + il) * 2];
                    sth = trig[(row * 32 + il) * 2 + 1];
                } else { cth = 1.f; sth = 0.f; }
                const float partner = tile[row * 132 + (d < 64 ? d + 64 : d - 64)] * sc;
                out[e] = (d < 64) ? (n * cth + partner * sth)
                                  : (n * cth - partner * sth);
            }
            const int m = m0 + row;
            const int b = m >> 11, t = m & (SEQ - 1);
            const size_t o = (((size_t)(b * NH + h)) * SEQ + t) * HD + dd;
            if (kind == 0) *(uint32_t*)(Qg + o) = packh(out[0], out[1]);
            else           *(uint32_t*)(Kg + o) = packh(out[0], out[1]);
        }
    } else {
        const float l0 = lam[0], l1 = lam[1];
        __syncthreads();
        for (int e = tid; e < 32768; e += 512) {
            const int row = e >> 7, d = e & 127;
            const int m = m0 + row;
            const float vv = ve[(size_t)m * HDIM + h * HD + d];
            tile[row * 132 + d] = l0 * tile[row * 132 + d] + l1 * vv;
        }
        __syncthreads();
        const int d = tid >> 2;
        const int tq = (tid & 3) * 64;
        const int b = m0 >> 11, tbase = m0 & (SEQ - 1);
        const size_t obase = (((size_t)(b * NH + h)) * HD + d) * SEQ + tbase + tq;
#pragma unroll 8
        for (int k = 0; k < 64; k += 2) {
            const float v0 = tile[(tq + k) * 132 + d];
            const float v1 = tile[(tq + k + 1) * 132 + d];
            *(uint32_t*)(Vg + obase + k) = packh(v0, v1);
        }
    }
}

// ===========================================================================
// Flash attention, single fp16. 128 q-rows/CTA, 8 warps x 16 rows.
// Q resident; K/V 4-stage cp.async (prefetch before wait).
// ===========================================================================
#define FQ_PART 34816
#define FK_PART 17408
#define FV_PART 18432
#define FSTAGE  (FK_PART + FV_PART)               // 35840
#define F_SMEM  (FQ_PART + 4 * FSTAGE)            // 178176

__global__ __launch_bounds__(256, 1) void flash_mma(
    const __half* __restrict__ Qg, const __half* __restrict__ Kg,
    const __half* __restrict__ Vg, __half* __restrict__ Yg)
{
    extern __shared__ char smem[];
    const uint32_t sbase = smem_u32(smem);
    const int tid = threadIdx.x;
    const int wid = tid >> 5, lane = tid & 31;
    const int qt = gridDim.x - 1 - blockIdx.x;      // big tiles first
    const int bh = blockIdx.y;
    const int b = bh >> 3, h = bh & 7;

    const size_t TD = (size_t)SEQ * HD;
    const __half* q_b = Qg + bh * TD;
    const __half* k_b = Kg + bh * TD;
    const __half* v_b = Vg + bh * TD;

#pragma unroll
    for (int i = 0; i < 8; i++) {
        int c = i * 256 + tid;
        int row = c >> 4, col = c & 15;
        CP_ASYNC16(sbase + row * 272 + col * 16,
                   q_b + (size_t)(qt * 128 + row) * 128 + col * 8);
    }
    auto load_kv = [&](int kt, int s) {
        uint32_t kb = sbase + FQ_PART + s * FSTAGE;
#pragma unroll
        for (int i = 0; i < 4; i++) {
            int c = i * 256 + tid;
            int row = c >> 4, col = c & 15;
            CP_ASYNC16(kb + row * 272 + col * 16,
                       k_b + (size_t)(kt * 64 + row) * 128 + col * 8);
        }
#pragma unroll
        for (int i = 0; i < 4; i++) {
            int c = i * 256 + tid;
            int row = c >> 3, col = c & 7;
            CP_ASYNC16(kb + FK_PART + row * 144 + col * 16,
                       v_b + (size_t)row * SEQ + kt * 64 + col * 8);
        }
    };
    const int nkt = 2 * qt + 2;
    load_kv(0, 0);
    CP_COMMIT();
    if (nkt > 1) { load_kv(1, 1); CP_COMMIT(); }
    if (nkt > 2) { load_kv(2, 2); CP_COMMIT(); }

    float acc[16][4];
#pragma unroll
    for (int i = 0; i < 16; i++)
#pragma unroll
        for (int e = 0; e < 4; e++) acc[i][e] = 0.f;
    float m_i[2] = {-1e30f, -1e30f};
    float l_i[2] = {0.f, 0.f};

    const uint32_t lrow = lane & 15;
    const uint32_t lcol = (lane >> 4) * 16;
    const float SC = 0.08838834764831845f;

    for (int kt = 0; kt < nkt; kt++) {
        if (kt + 3 < nkt) {
            load_kv(kt + 3, (kt + 3) & 3);
            CP_COMMIT();
            CP_WAIT3();
        } else if (kt + 2 < nkt) {
            CP_WAIT2();
        } else if (kt + 1 < nkt) {
            CP_WAIT1();
        } else {
            CP_WAIT0();
        }
        __syncthreads();
        const uint32_t kb = sbase + FQ_PART + (kt & 3) * FSTAGE;

        float s[8][4];
#pragma unroll
        for (int j = 0; j < 8; j++)
#pragma unroll
            for (int e = 0; e < 4; e++) s[j][e] = 0.f;

        const uint32_t qrow = sbase + (wid * 16 + lrow) * 272 + lcol;
#pragma unroll
        for (int k16 = 0; k16 < 8; k16++) {
            uint32_t a_[4];
            LDMX4(a_, qrow + k16 * 32);
            uint32_t kf[4][4];
#pragma unroll
            for (int jj = 0; jj < 4; jj++)
                LDMX4(kf[jj], kb + (jj * 16 + lrow) * 272 + lcol + k16 * 32);
#pragma unroll
            for (int jj = 0; jj < 4; jj++) {
                MMA_F16(s[2 * jj], a_, kf[jj][0], kf[jj][2]);
                MMA_F16(s[2 * jj + 1], a_, kf[jj][1], kf[jj][3]);
            }
        }

        const bool need_mask = (kt >= 2 * qt);
#pragma unroll
        for (int hh = 0; hh < 2; hh++) {
            const int rowg = qt * 128 + wid * 16 + (lane >> 2) + hh * 8;
            float mt = -1e30f;
#pragma unroll
            for (int j = 0; j < 8; j++) {
#pragma unroll
                for (int e = 0; e < 2; e++) {
                    float v = s[j][2 * hh + e] * SC;
                    if (need_mask) {
                        int colg = kt * 64 + j * 8 + (lane & 3) * 2 + e;
                        if (colg > rowg) v = -1e30f;
                    }
                    s[j][2 * hh + e] = v;
                    mt = fmaxf(mt, v);
                }
            }
            mt = fmaxf(mt, __shfl_xor_sync(0xffffffffu, mt, 1));
            mt = fmaxf(mt, __shfl_xor_sync(0xffffffffu, mt, 2));
            float mn = fmaxf(m_i[hh], mt);
            float corr = __expf(m_i[hh] - mn);
            m_i[hh] = mn;
            float rs = 0.f;
#pragma unroll
            for (int j = 0; j < 8; j++) {
#pragma unroll
                for (int e = 0; e < 2; e++) {
                    float p = __expf(s[j][2 * hh + e] - mn);
                    s[j][2 * hh + e] = p;
                    rs += p;
                }
            }
            rs += __shfl_xor_sync(0xffffffffu, rs, 1);
            rs += __shfl_xor_sync(0xffffffffu, rs, 2);
            l_i[hh] = l_i[hh] * corr + rs;
#pragma unroll
            for (int ot = 0; ot < 16; ot++) {
                acc[ot][2 * hh] *= corr;
                acc[ot][2 * hh + 1] *= corr;
            }
        }

        const uint32_t vb = kb + FK_PART;
#pragma unroll
        for (int kk = 0; kk < 4; kk++) {
            const int j0 = 2 * kk, j1 = 2 * kk + 1;
            uint32_t p_[4];
            p_[0] = packh(s[j0][0], s[j0][1]);
            p_[1] = packh(s[j0][2], s[j0][3]);
            p_[2] = packh(s[j1][0], s[j1][1]);
            p_[3] = packh(s[j1][2], s[j1][3]);
#pragma unroll
            for (int jp = 0; jp < 4; jp++) {
                const int ja = 2 * jp, jb2 = 2 * jp + 1;
                uint32_t rA[4], rB[4];
                LDMX4(rA, vb + (ja * 16 + lrow) * 144 + kk * 32 + lcol);
                LDMX4(rB, vb + (jb2 * 16 + lrow) * 144 + kk * 32 + lcol);
                MMA_F16(acc[2 * ja], p_, rA[0], rA[2]);
                MMA_F16(acc[2 * ja + 1], p_, rA[1], rA[3]);
                MMA_F16(acc[2 * jb2], p_, rB[0], rB[2]);
                MMA_F16(acc[2 * jb2 + 1], p_, rB[1], rB[3]);
            }
        }
        __syncthreads();
    }

    const float inv0 = 1.f / l_i[0];
    const float inv1 = 1.f / l_i[1];
    const int r0 = qt * 128 + wid * 16 + (lane >> 2);
    const int cb = (lane & 3) * 2;
#pragma unroll
    for (int ot = 0; ot < 16; ot++) {
        const int d = ot * 8 + cb;
        size_t o0 = ((size_t)b * SEQ + r0) * HDIM + h * HD + d;
        size_t o1 = o0 + (size_t)8 * HDIM;
        *(uint32_t*)(Yg + o0) = packh(acc[ot][0] * inv0, acc[ot][1] * inv0);
        *(uint32_t*)(Yg + o1) = packh(acc[ot][2] * inv1, acc[ot][3] * inv1);
    }
}

// ---------------------------------------------------------------------------
extern "C" void kernel_launch(void* const* d_in, const int* in_sizes, int n_in,
                              void* d_out, int out_size)
{
    const float* x        = (const float*)d_in[0];
    const float* ve       = (const float*)d_in[1];
    const float* qkv_w    = (const float*)d_in[2];   // [3*HDIM, DIM]
    const float* lambdas  = (const float*)d_in[3];
    const float* c_proj_w = (const float*)d_in[4];   // [DIM, HDIM]
    float* out = (float*)d_out;

    __half *Q, *K, *V, *X, *Wq, *Wp, *Y;
    float* Tg;
    cudaGetSymbolAddress((void**)&Q, g_q);
    cudaGetSymbolAddress((void**)&K, g_k);
    cudaGetSymbolAddress((void**)&V, g_v);
    cudaGetSymbolAddress((void**)&X, g_x);
    cudaGetSymbolAddress((void**)&Wq, g_wq);
    cudaGetSymbolAddress((void**)&Wp, g_wp);
    cudaGetSymbolAddress((void**)&Y, g_y);
    cudaGetSymbolAddress((void**)&Tg, g_trig);

    cudaFuncSetAttribute(gemm_f16, cudaFuncAttributeMaxDynamicSharedMemorySize, G_SMEM);
    cudaFuncSetAttribute(flash_mma, cudaFuncAttributeMaxDynamicSharedMemorySize, F_SMEM);

    // 0) merged prologue: fp16 conversions + trig table (single launch)
    prep_all<<<PB_ALL, 256>>>(x, X, qkv_w, Wq, c_proj_w, Wp, Tg);

    // 1) fused qkv GEMM + rms/rope/v-mix/layout -> Q,K,V
    gemm_f16<<<dim3(3 * HDIM / 128, BATCH * SEQ / 256), 512, G_SMEM>>>(
        X, Wq, nullptr, DMODEL, 3 * HDIM, 1, Q, K, V, ve, lambdas, Tg);

    // 2) flash attention (128 q-rows/CTA, 4-stage KV pipeline) -> Y (fp16)
    flash_mma<<<dim3(SEQ / 128, BATCH * NH), 256, F_SMEM>>>(Q, K, V, Y);

    // 3) out = Y @ c_proj_w^T
    gemm_f16<<<dim3(DMODEL / 128, BATCH * SEQ / 256), 512, G_SMEM>>>(
        Y, Wp, out, HDIM, DMODEL, 0,
        nullptr, nullptr, nullptr, nullptr, nullptr, nullptr);
}

// round 17
// speedup vs baseline: 1.0103x; 1.0013x over previous
#include <cuda_runtime.h>
#include <cuda_fp16.h>
#include <cstdint>
#include <math.h>

#define BATCH 4
#define SEQ   2048
#define DMODEL 1024
#define NH    8
#define HD    128
#define HDIM  1024

// ---------------------------------------------------------------------------
// Scratch (device globals: allocation-free rule)
// ---------------------------------------------------------------------------
__device__ __half g_q[(size_t)BATCH * NH * SEQ * HD];        // [B,H,T,D]
__device__ __half g_k[(size_t)BATCH * NH * SEQ * HD];
__device__ __half g_v[(size_t)BATCH * NH * HD * SEQ];        // [B,H,D,T]
__device__ __half g_x[(size_t)BATCH * SEQ * DMODEL];
__device__ __half g_wq[(size_t)3 * HDIM * DMODEL];
__device__ __half g_wp[(size_t)DMODEL * HDIM];
__device__ __half g_y[(size_t)BATCH * SEQ * HDIM];
__device__ float  g_trig[(size_t)SEQ * 64];                  // [t][32][{cos,sin}]

// ---------------------------------------------------------------------------
// PTX helpers
// ---------------------------------------------------------------------------
__device__ __forceinline__ uint32_t smem_u32(const void* p) {
    uint32_t a;
    asm("{ .reg .u64 t; cvta.to.shared.u64 t, %1; cvt.u32.u64 %0, t; }"
        : "=r"(a) : "l"(p));
    return a;
}

#define LDMX4(r, addr) \
    asm volatile("ldmatrix.sync.aligned.m8n8.x4.shared.b16 {%0,%1,%2,%3}, [%4];" \
        : "=r"((r)[0]), "=r"((r)[1]), "=r"((r)[2]), "=r"((r)[3]) : "r"(addr))

#define MMA_F16(d, a, b0, b1) \
    asm volatile("mma.sync.aligned.m16n8k16.row.col.f32.f16.f16.f32 " \
        "{%0,%1,%2,%3},{%4,%5,%6,%7},{%8,%9},{%0,%1,%2,%3};" \
        : "+f"((d)[0]), "+f"((d)[1]), "+f"((d)[2]), "+f"((d)[3]) \
        : "r"((a)[0]), "r"((a)[1]), "r"((a)[2]), "r"((a)[3]), "r"(b0), "r"(b1))

#define CP_ASYNC16(dst, src) \
    asm volatile("cp.async.cg.shared.global [%0], [%1], 16;" :: "r"(dst), "l"(src) : "memory")
#define CP_COMMIT() asm volatile("cp.async.commit_group;" ::: "memory")
#define CP_WAIT0()  asm volatile("cp.async.wait_group 0;" ::: "memory")
#define CP_WAIT1()  asm volatile("cp.async.wait_group 1;" ::: "memory")
#define CP_WAIT2()  asm volatile("cp.async.wait_group 2;" ::: "memory")
#define CP_WAIT3()  asm volatile("cp.async.wait_group 3;" ::: "memory")

__device__ __forceinline__ uint32_t packh(float e0, float e1) {
    __half2 h = __floats2half2_rn(e0, e1);
    return *reinterpret_cast<uint32_t*>(&h);
}

// ---------------------------------------------------------------------------
// prep_all: merged fp32->fp16 conversions (x, Wq, Wp) + RoPE trig table.
// ---------------------------------------------------------------------------
#define PB_X   8192
#define PB_WQ  3072
#define PB_WP  1024
#define PB_TR  256
#define PB_ALL (PB_X + PB_WQ + PB_WP + PB_TR)

__global__ __launch_bounds__(256) void prep_all(
    const float* __restrict__ x,  __half* __restrict__ X,
    const float* __restrict__ wq, __half* __restrict__ Wq,
    const float* __restrict__ wp, __half* __restrict__ Wp,
    float* __restrict__ tg)
{
    const int blk = blockIdx.x;
    if (blk < PB_X + PB_WQ + PB_WP) {
        const float* src;
        __half* dst;
        int i;
        if (blk < PB_X) {
            src = x; dst = X; i = blk * 256 + threadIdx.x;
        } else if (blk < PB_X + PB_WQ) {
            src = wq; dst = Wq; i = (blk - PB_X) * 256 + threadIdx.x;
        } else {
            src = wp; dst = Wp; i = (blk - PB_X - PB_WQ) * 256 + threadIdx.x;
        }
        float4 v = ((const float4*)src)[i];
        ((uint2*)dst)[i] = make_uint2(packh(v.x, v.y), packh(v.z, v.w));
    } else {
        const int idx = (blk - PB_X - PB_WQ - PB_WP) * 256 + threadIdx.x;
        const int t = idx >> 5, i = idx & 31;
        const float xi = (float)i / 31.0f;
        const float f = (float)exp2(-10.0 * (double)xi);
        const float th = (float)t * f;
        tg[t * 64 + i * 2]     = cosf(th);
        tg[t * 64 + i * 2 + 1] = sinf(th);
    }
}

// ===========================================================================
// fp16 GEMM (fused qkv variant): CTA 256x128, 512 thr, K-chunk 32, 4-stage.
// ===========================================================================
#define GA_PART  20480
#define GB_PART  10240
#define G_STAGE  (GA_PART + GB_PART)              // 30720
#define G_SMEM   204800                           // epilogue tile needs 201728

__global__ __launch_bounds__(512, 1) void gemm_f16(
    const __half* __restrict__ A, const __half* __restrict__ B,
    float* __restrict__ C, int Kd, int Nd, int fused,
    __half* __restrict__ Qg, __half* __restrict__ Kg, __half* __restrict__ Vg,
    const float* __restrict__ ve, const float* __restrict__ lam,
    const float* __restrict__ trig_g)
{
    extern __shared__ char smem[];
    const uint32_t sb = smem_u32(smem);
    const int tid = threadIdx.x;
    const int wid = tid >> 5, lane = tid & 31;
    const int wm = wid >> 2, wn = wid & 3;
    const int m0 = blockIdx.y * 256, n0 = blockIdx.x * 128;
    const int nch = Kd / 32;

    auto load_stage = [&](int c) {
        const uint32_t st = sb + (c & 3) * G_STAGE;
        const __half* pA = A + (size_t)m0 * Kd + c * 32;
        const __half* pB = B + (size_t)n0 * Kd + c * 32;
#pragma unroll
        for (int i = 0; i < 2; i++) {
            const int cc = i * 512 + tid;
            const int row = cc >> 2, col = cc & 3;
            CP_ASYNC16(st + row * 80 + col * 16, pA + (size_t)row * Kd + col * 8);
        }
        {
            const int row = tid >> 2, col = tid & 3;
            CP_ASYNC16(st + GA_PART + row * 80 + col * 16, pB + (size_t)row * Kd + col * 8);
        }
    };

    float acc[4][4][4];
#pragma unroll
    for (int i = 0; i < 4; i++)
#pragma unroll
        for (int j = 0; j < 4; j++)
#pragma unroll
            for (int e = 0; e < 4; e++) acc[i][j][e] = 0.f;

    auto compute = [&](int s) {
        const uint32_t st = sb + s * G_STAGE;
        const uint32_t lrow = (lane & 15);
        const uint32_t lcol = (lane >> 4) * 16;
#pragma unroll
        for (int k16 = 0; k16 < 2; k16++) {
            const uint32_t kb2 = k16 * 32;
            uint32_t a_[4][4];
#pragma unroll
            for (int i = 0; i < 4; i++)
                LDMX4(a_[i], st + (wm * 64 + i * 16 + lrow) * 80 + kb2 + lcol);
            uint32_t b_[4][2];
#pragma unroll
            for (int jj = 0; jj < 2; jj++) {
                uint32_t r[4];
                LDMX4(r, st + GA_PART + (wn * 32 + jj * 16 + lrow) * 80 + kb2 + lcol);
                b_[2 * jj][0] = r[0]; b_[2 * jj][1] = r[2];
                b_[2 * jj + 1][0] = r[1]; b_[2 * jj + 1][1] = r[3];
            }
#pragma unroll
            for (int i = 0; i < 4; i++)
#pragma unroll
                for (int j = 0; j < 4; j++)
                    MMA_F16(acc[i][j], a_[i], b_[j][0], b_[j][1]);
        }
    };

    load_stage(0); CP_COMMIT();
    load_stage(1); CP_COMMIT();
    load_stage(2); CP_COMMIT();
    for (int c = 0; c < nch; c++) {
        if (c + 2 < nch) CP_WAIT2();
        else if (c + 1 < nch) CP_WAIT1();
        else CP_WAIT0();
        __syncthreads();
        if (c + 3 < nch) { load_stage(c + 3); CP_COMMIT(); }
        compute(c & 3);
    }

    const int r = lane >> 2;
    const int cb = (lane & 3) * 2;

    if (!fused) {
#pragma unroll
        for (int i = 0; i < 4; i++) {
            const int row0 = m0 + wm * 64 + i * 16 + r;
#pragma unroll
            for (int j = 0; j < 4; j++) {
                const int col = n0 + wn * 32 + j * 8 + cb;
                *(float2*)(C + (size_t)row0 * Nd + col) = make_float2(acc[i][j][0], acc[i][j][1]);
                *(float2*)(C + (size_t)(row0 + 8) * Nd + col) = make_float2(acc[i][j][2], acc[i][j][3]);
            }
        }
        return;
    }

    // ======================= fused qkv epilogue ==========================
    float* tile = (float*)smem;              // [256][132]
    float* rsc  = tile + 256 * 132;          // [256]
    float* trig = rsc + 256;                 // [256][32][2]

    __syncthreads();

#pragma unroll
    for (int i = 0; i < 4; i++) {
        const int row = wm * 64 + i * 16 + r;
#pragma unroll
        for (int j = 0; j < 4; j++) {
            const int col = wn * 32 + j * 8 + cb;
            *(float2*)(tile + row * 132 + col) = make_float2(acc[i][j][0], acc[i][j][1]);
            *(float2*)(tile + (row + 8) * 132 + col) = make_float2(acc[i][j][2], acc[i][j][3]);
        }
    }

    const int part = n0 >> 7;        // 0..23
    const int kind = part >> 3;      // 0=q 1=k 2=v
    const int h = part & 7;

    if (kind < 2) {
        __syncthreads();
        {
            const int row = tid >> 1, hs = tid & 1;
            const float* tr = tile + row * 132 + hs * 64;
            float s = 0.f;
#pragma unroll
            for (int k4 = 0; k4 < 16; k4++) {
                float4 v = *(const float4*)(tr + k4 * 4);
                s += v.x * v.x + v.y * v.y + v.z * v.z + v.w * v.w;
            }
            s += __shfl_xor_sync(0xffffffffu, s, 1);
            if (hs == 0)
                rsc[row] = rsqrtf(s * (1.0f / 128.0f) + 1.1920929e-7f);
        }
        for (int e = tid; e < 8192; e += 512) {
            const int row = e >> 5, i = e & 31;
            const int t = (m0 + row) & (SEQ - 1);
            ((float2*)trig)[e] = ((const float2*)trig_g)[t * 32 + i];
        }
        __syncthreads();

        const int dd = (tid & 63) * 2;
        const int rg = tid >> 6;
#pragma unroll 4
        for (int stp = 0; stp < 32; stp++) {
            const int row = rg + stp * 8;
            const float sc = rsc[row];
            float out[2];
#pragma unroll
            for (int e = 0; e < 2; e++) {
                const int d = dd + e;
                const float n = tile[row * 132 + d] * sc;
                const int il = d & 63;
                float cth, sth;
                if (il < 32) {
                    cth = trig[(row * 32 + il) * 2];
                    sth = trig[(row * 32 + il) * 2 + 1];
                } else { cth = 1.f; sth = 0.f; }
                const float partner = tile[row * 132 + (d < 64 ? d + 64 : d - 64)] * sc;
                out[e] = (d < 64) ? (n * cth + partner * sth)
                                  : (n * cth - partner * sth);
            }
            const int m = m0 + row;
            const int b = m >> 11, t = m & (SEQ - 1);
            const size_t o = (((size_t)(b * NH + h)) * SEQ + t) * HD + dd;
            if (kind == 0) *(uint32_t*)(Qg + o) = packh(out[0], out[1]);
            else           *(uint32_t*)(Kg + o) = packh(out[0], out[1]);
        }
    } else {
        const float l0 = lam[0], l1 = lam[1];
        __syncthreads();
        for (int e = tid; e < 32768; e += 512) {
            const int row = e >> 7, d = e & 127;
            const int m = m0 + row;
            const float vv = ve[(size_t)m * HDIM + h * HD + d];
            tile[row * 132 + d] = l0 * tile[row * 132 + d] + l1 * vv;
        }
        __syncthreads();
        const int d = tid >> 2;
        const int tq = (tid & 3) * 64;
        const int b = m0 >> 11, tbase = m0 & (SEQ - 1);
        const size_t obase = (((size_t)(b * NH + h)) * HD + d) * SEQ + tbase + tq;
#pragma unroll 8
        for (int k = 0; k < 64; k += 2) {
            const float v0 = tile[(tq + k) * 132 + d];
            const float v1 = tile[(tq + k + 1) * 132 + d];
            *(uint32_t*)(Vg + obase + k) = packh(v0, v1);
        }
    }
}

// ===========================================================================
// fp16 GEMM (c_proj variant): CTA 128x128, 256 thr (8 warps 2x4), K-chunk 32,
// 4-stage cp.async. Stage = 20480 B; 4 stages = 81920 -> 2 CTAs/SM.
// Finer tiles: grid 512 vs 256 -> less tail quantization.
// ===========================================================================
#define H_PART   10240
#define H_STAGE  20480
#define H_SMEM   (4 * H_STAGE)                    // 81920

__global__ __launch_bounds__(256, 2) void gemm_f16_128(
    const __half* __restrict__ A, const __half* __restrict__ B,
    float* __restrict__ C, int Kd, int Nd)
{
    extern __shared__ char smem[];
    const uint32_t sb = smem_u32(smem);
    const int tid = threadIdx.x;
    const int wid = tid >> 5, lane = tid & 31;
    const int wm = wid >> 2, wn = wid & 3;        // 2x4 warp grid
    const int m0 = blockIdx.y * 128, n0 = blockIdx.x * 128;
    const int nch = Kd / 32;

    auto load_stage = [&](int c) {
        const uint32_t st = sb + (c & 3) * H_STAGE;
        const __half* pA = A + (size_t)m0 * Kd + c * 32;
        const __half* pB = B + (size_t)n0 * Kd + c * 32;
#pragma unroll
        for (int i = 0; i < 2; i++) {
            const int cc = i * 256 + tid;          // 0..511
            const int row = cc >> 2, col = cc & 3;
            const uint32_t off = row * 80 + col * 16;
            const size_t gi = (size_t)row * Kd + col * 8;
            CP_ASYNC16(st + off,          pA + gi);
            CP_ASYNC16(st + H_PART + off, pB + gi);
        }
    };

    float acc[4][4][4];
#pragma unroll
    for (int i = 0; i < 4; i++)
#pragma unroll
        for (int j = 0; j < 4; j++)
#pragma unroll
            for (int e = 0; e < 4; e++) acc[i][j][e] = 0.f;

    auto compute = [&](int s) {
        const uint32_t st = sb + s * H_STAGE;
        const uint32_t lrow = (lane & 15);
        const uint32_t lcol = (lane >> 4) * 16;
#pragma unroll
        for (int k16 = 0; k16 < 2; k16++) {
            const uint32_t kb2 = k16 * 32;
            uint32_t a_[4][4];
#pragma unroll
            for (int i = 0; i < 4; i++)
                LDMX4(a_[i], st + (wm * 64 + i * 16 + lrow) * 80 + kb2 + lcol);
            uint32_t b_[4][2];
#pragma unroll
            for (int jj = 0; jj < 2; jj++) {
                uint32_t r[4];
                LDMX4(r, st + H_PART + (wn * 32 + jj * 16 + lrow) * 80 + kb2 + lcol);
                b_[2 * jj][0] = r[0]; b_[2 * jj][1] = r[2];
                b_[2 * jj + 1][0] = r[1]; b_[2 * jj + 1][1] = r[3];
            }
#pragma unroll
            for (int i = 0; i < 4; i++)
#pragma unroll
                for (int j = 0; j < 4; j++)
                    MMA_F16(acc[i][j], a_[i], b_[j][0], b_[j][1]);
        }
    };

    load_stage(0); CP_COMMIT();
    load_stage(1); CP_COMMIT();
    load_stage(2); CP_COMMIT();
    for (int c = 0; c < nch; c++) {
        if (c + 2 < nch) CP_WAIT2();
        else if (c + 1 < nch) CP_WAIT1();
        else CP_WAIT0();
        __syncthreads();
        if (c + 3 < nch) { load_stage(c + 3); CP_COMMIT(); }
        compute(c & 3);
    }

    const int r = lane >> 2;
    const int cb = (lane & 3) * 2;
#pragma unroll
    for (int i = 0; i < 4; i++) {
        const int row0 = m0 + wm * 64 + i * 16 + r;
#pragma unroll
        for (int j = 0; j < 4; j++) {
            const int col = n0 + wn * 32 + j * 8 + cb;
            *(float2*)(C + (size_t)row0 * Nd + col) = make_float2(acc[i][j][0], acc[i][j][1]);
            *(float2*)(C + (size_t)(row0 + 8) * Nd + col) = make_float2(acc[i][j][2], acc[i][j][3]);
        }
    }
}

// ===========================================================================
// Flash attention, single fp16. 128 q-rows/CTA, 8 warps x 16 rows.
// Q resident; K/V 4-stage cp.async (prefetch before wait).
// ===========================================================================
#define FQ_PART 34816
#define FK_PART 17408
#define FV_PART 18432
#define FSTAGE  (FK_PART + FV_PART)               // 35840
#define F_SMEM  (FQ_PART + 4 * FSTAGE)            // 178176

__global__ __launch_bounds__(256, 1) void flash_mma(
    const __half* __restrict__ Qg, const __half* __restrict__ Kg,
    const __half* __restrict__ Vg, __half* __restrict__ Yg)
{
    extern __shared__ char smem[];
    const uint32_t sbase = smem_u32(smem);
    const int tid = threadIdx.x;
    const int wid = tid >> 5, lane = tid & 31;
    const int qt = gridDim.x - 1 - blockIdx.x;      // big tiles first
    const int bh = blockIdx.y;
    const int b = bh >> 3, h = bh & 7;

    const size_t TD = (size_t)SEQ * HD;
    const __half* q_b = Qg + bh * TD;
    const __half* k_b = Kg + bh * TD;
    const __half* v_b = Vg + bh * TD;

#pragma unroll
    for (int i = 0; i < 8; i++) {
        int c = i * 256 + tid;
        int row = c >> 4, col = c & 15;
        CP_ASYNC16(sbase + row * 272 + col * 16,
                   q_b + (size_t)(qt * 128 + row) * 128 + col * 8);
    }
    auto load_kv = [&](int kt, int s) {
        uint32_t kb = sbase + FQ_PART + s * FSTAGE;
#pragma unroll
        for (int i = 0; i < 4; i++) {
            int c = i * 256 + tid;
            int row = c >> 4, col = c & 15;
            CP_ASYNC16(kb + row * 272 + col * 16,
                       k_b + (size_t)(kt * 64 + row) * 128 + col * 8);
        }
#pragma unroll
        for (int i = 0; i < 4; i++) {
            int c = i * 256 + tid;
            int row = c >> 3, col = c & 7;
            CP_ASYNC16(kb + FK_PART + row * 144 + col * 16,
                       v_b + (size_t)row * SEQ + kt * 64 + col * 8);
        }
    };
    const int nkt = 2 * qt + 2;
    load_kv(0, 0);
    CP_COMMIT();
    if (nkt > 1) { load_kv(1, 1); CP_COMMIT(); }
    if (nkt > 2) { load_kv(2, 2); CP_COMMIT(); }

    float acc[16][4];
#pragma unroll
    for (int i = 0; i < 16; i++)
#pragma unroll
        for (int e = 0; e < 4; e++) acc[i][e] = 0.f;
    float m_i[2] = {-1e30f, -1e30f};
    float l_i[2] = {0.f, 0.f};

    const uint32_t lrow = lane & 15;
    const uint32_t lcol = (lane >> 4) * 16;
    const float SC = 0.08838834764831845f;

    for (int kt = 0; kt < nkt; kt++) {
        if (kt + 3 < nkt) {
            load_kv(kt + 3, (kt + 3) & 3);
            CP_COMMIT();
            CP_WAIT3();
        } else if (kt + 2 < nkt) {
            CP_WAIT2();
        } else if (kt + 1 < nkt) {
            CP_WAIT1();
        } else {
            CP_WAIT0();
        }
        __syncthreads();
        const uint32_t kb = sbase + FQ_PART + (kt & 3) * FSTAGE;

        float s[8][4];
#pragma unroll
        for (int j = 0; j < 8; j++)
#pragma unroll
            for (int e = 0; e < 4; e++) s[j][e] = 0.f;

        const uint32_t qrow = sbase + (wid * 16 + lrow) * 272 + lcol;
#pragma unroll
        for (int k16 = 0; k16 < 8; k16++) {
            uint32_t a_[4];
            LDMX4(a_, qrow + k16 * 32);
            uint32_t kf[4][4];
#pragma unroll
            for (int jj = 0; jj < 4; jj++)
                LDMX4(kf[jj], kb + (jj * 16 + lrow) * 272 + lcol + k16 * 32);
#pragma unroll
            for (int jj = 0; jj < 4; jj++) {
                MMA_F16(s[2 * jj], a_, kf[jj][0], kf[jj][2]);
                MMA_F16(s[2 * jj + 1], a_, kf[jj][1], kf[jj][3]);
            }
        }

        const bool need_mask = (kt >= 2 * qt);
#pragma unroll
        for (int hh = 0; hh < 2; hh++) {
            const int rowg = qt * 128 + wid * 16 + (lane >> 2) + hh * 8;
            float mt = -1e30f;
#pragma unroll
            for (int j = 0; j < 8; j++) {
#pragma unroll
                for (int e = 0; e < 2; e++) {
                    float v = s[j][2 * hh + e] * SC;
                    if (need_mask) {
                        int colg = kt * 64 + j * 8 + (lane & 3) * 2 + e;
                        if (colg > rowg) v = -1e30f;
                    }
                    s[j][2 * hh + e] = v;
                    mt = fmaxf(mt, v);
                }
            }
            mt = fmaxf(mt, __shfl_xor_sync(0xffffffffu, mt, 1));
            mt = fmaxf(mt, __shfl_xor_sync(0xffffffffu, mt, 2));
            float mn = fmaxf(m_i[hh], mt);
            float corr = __expf(m_i[hh] - mn);
            m_i[hh] = mn;
            float rs = 0.f;
#pragma unroll
            for (int j = 0; j < 8; j++) {
#pragma unroll
                for (int e = 0; e < 2; e++) {
                    float p = __expf(s[j][2 * hh + e] - mn);
                    s[j][2 * hh + e] = p;
                    rs += p;
                }
            }
            rs += __shfl_xor_sync(0xffffffffu, rs, 1);
            rs += __shfl_xor_sync(0xffffffffu, rs, 2);
            l_i[hh] = l_i[hh] * corr + rs;
#pragma unroll
            for (int ot = 0; ot < 16; ot++) {
                acc[ot][2 * hh] *= corr;
                acc[ot][2 * hh + 1] *= corr;
            }
        }

        const uint32_t vb = kb + FK_PART;
#pragma unroll
        for (int kk = 0; kk < 4; kk++) {
            const int j0 = 2 * kk, j1 = 2 * kk + 1;
            uint32_t p_[4];
            p_[0] = packh(s[j0][0], s[j0][1]);
            p_[1] = packh(s[j0][2], s[j0][3]);
            p_[2] = packh(s[j1][0], s[j1][1]);
            p_[3] = packh(s[j1][2], s[j1][3]);
#pragma unroll
            for (int jp = 0; jp < 4; jp++) {
                const int ja = 2 * jp, jb2 = 2 * jp + 1;
                uint32_t rA[4], rB[4];
                LDMX4(rA, vb + (ja * 16 + lrow) * 144 + kk * 32 + lcol);
                LDMX4(rB, vb + (jb2 * 16 + lrow) * 144 + kk * 32 + lcol);
                MMA_F16(acc[2 * ja], p_, rA[0], rA[2]);
                MMA_F16(acc[2 * ja + 1], p_, rA[1], rA[3]);
                MMA_F16(acc[2 * jb2], p_, rB[0], rB[2]);
                MMA_F16(acc[2 * jb2 + 1], p_, rB[1], rB[3]);
            }
        }
        __syncthreads();
    }

    const float inv0 = 1.f / l_i[0];
    const float inv1 = 1.f / l_i[1];
    const int r0 = qt * 128 + wid * 16 + (lane >> 2);
    const int cb = (lane & 3) * 2;
#pragma unroll
    for (int ot = 0; ot < 16; ot++) {
        const int d = ot * 8 + cb;
        size_t o0 = ((size_t)b * SEQ + r0) * HDIM + h * HD + d;
        size_t o1 = o0 + (size_t)8 * HDIM;
        *(uint32_t*)(Yg + o0) = packh(acc[ot][0] * inv0, acc[ot][1] * inv0);
        *(uint32_t*)(Yg + o1) = packh(acc[ot][2] * inv1, acc[ot][3] * inv1);
    }
}

// ---------------------------------------------------------------------------
extern "C" void kernel_launch(void* const* d_in, const int* in_sizes, int n_in,
                              void* d_out, int out_size)
{
    const float* x        = (const float*)d_in[0];
    const float* ve       = (const float*)d_in[1];
    const float* qkv_w    = (const float*)d_in[2];   // [3*HDIM, DIM]
    const float* lambdas  = (const float*)d_in[3];
    const float* c_proj_w = (const float*)d_in[4];   // [DIM, HDIM]
    float* out = (float*)d_out;

    __half *Q, *K, *V, *X, *Wq, *Wp, *Y;
    float* Tg;
    cudaGetSymbolAddress((void**)&Q, g_q);
    cudaGetSymbolAddress((void**)&K, g_k);
    cudaGetSymbolAddress((void**)&V, g_v);
    cudaGetSymbolAddress((void**)&X, g_x);
    cudaGetSymbolAddress((void**)&Wq, g_wq);
    cudaGetSymbolAddress((void**)&Wp, g_wp);
    cudaGetSymbolAddress((void**)&Y, g_y);
    cudaGetSymbolAddress((void**)&Tg, g_trig);

    cudaFuncSetAttribute(gemm_f16, cudaFuncAttributeMaxDynamicSharedMemorySize, G_SMEM);
    cudaFuncSetAttribute(gemm_f16_128, cudaFuncAttributeMaxDynamicSharedMemorySize, H_SMEM);
    cudaFuncSetAttribute(flash_mma, cudaFuncAttributeMaxDynamicSharedMemorySize, F_SMEM);

    // 0) merged prologue: fp16 conversions + trig table (single launch)
    prep_all<<<PB_ALL, 256>>>(x, X, qkv_w, Wq, c_proj_w, Wp, Tg);

    // 1) fused qkv GEMM + rms/rope/v-mix/layout -> Q,K,V
    gemm_f16<<<dim3(3 * HDIM / 128, BATCH * SEQ / 256), 512, G_SMEM>>>(
        X, Wq, nullptr, DMODEL, 3 * HDIM, 1, Q, K, V, ve, lambdas, Tg);

    // 2) flash attention (128 q-rows/CTA, 4-stage KV pipeline) -> Y (fp16)
    flash_mma<<<dim3(SEQ / 128, BATCH * NH), 256, F_SMEM>>>(Q, K, V, Y);

    // 3) out = Y @ c_proj_w^T  (128x128 tiles: 512 CTAs, 2 CTAs/SM)
    gemm_f16_128<<<dim3(DMODEL / 128, BATCH * SEQ / 128), 256, H_SMEM>>>(
        Y, Wp, out, HDIM, DMODEL);
}